// round 7
// baseline (speedup 1.0000x reference)
#include <cuda_runtime.h>
#include <cuda_bf16.h>
#include <stdint.h>
#include <math.h>

#define D 256
#define CHUNK 16
#define NTHREADS 256
#define MAXB 4100

// dynamic smem: 2 tiles + scores + w + red
#define SMEM_FLOATS (2 * CHUNK * D + 32 + D + 8)
#define SMEM_BYTES  (SMEM_FLOATS * 4)

__device__ int g_seg_start[MAXB];

// ---- kernel 1: segment boundaries from sorted batch (parallel diff-scatter) ----
__global__ void bounds_kernel(const int* __restrict__ batch, int N, int B) {
    int i = blockIdx.x * blockDim.x + threadIdx.x;
    if (i > N) return;
    int cur  = (i < N) ? batch[i]     : B;
    int prev = (i > 0) ? batch[i - 1] : -1;
    for (int b = prev + 1; b <= cur && b <= B; b++) g_seg_start[b] = i;
}

// ---- cp.async helpers ----
__device__ __forceinline__ void cp_async16(uint32_t dst_smem, const void* src) {
    asm volatile("cp.async.cg.shared.global [%0], [%1], 16;\n" :: "r"(dst_smem), "l"(src));
}
__device__ __forceinline__ void cp_commit() {
    asm volatile("cp.async.commit_group;\n");
}
__device__ __forceinline__ void cp_wait1() {
    asm volatile("cp.async.wait_group 1;\n");
}

__device__ __forceinline__ void stage_chunk(const float* __restrict__ x, int row0,
                                            int nrows, uint32_t buf_smem, int tid) {
    const char* src = reinterpret_cast<const char*>(x + (size_t)row0 * D);
    const int total = nrows * (D / 4);      // float4 count, <= 1024
    #pragma unroll
    for (int i = tid; i < total; i += NTHREADS)
        cp_async16(buf_smem + i * 16, src + (size_t)i * 16);
}

__global__ void __launch_bounds__(NTHREADS, 5)
niche_attn_kernel(const float* __restrict__ x,
                  const float* __restrict__ w,
                  const float* __restrict__ bptr,
                  float* __restrict__ out)
{
    extern __shared__ float smem[];
    float* tile0  = smem;                       // [CHUNK][D]
    float* tile1  = tile0 + CHUNK * D;          // [CHUNK][D]
    float* scores = tile1 + CHUNK * D;          // [32]
    float* wsh    = scores + 32;                // [D]

    const int seg  = blockIdx.x;
    const int tid  = threadIdx.x;
    const int lane = tid & 31;
    const int warp = tid >> 5;

    const int start = g_seg_start[seg];
    const int end   = g_seg_start[seg + 1];

    wsh[tid] = w[tid];
    const float bconst = bptr[0];

    const uint32_t buf_u32[2] = {
        (uint32_t)__cvta_generic_to_shared(tile0),
        (uint32_t)__cvta_generic_to_shared(tile1)
    };
    float* const bufs[2] = { tile0, tile1 };

    const int nch = (end - start + CHUNK - 1) / CHUNK;

    float m_run = -INFINITY;
    float s_run = 0.0f;
    float acc   = 0.0f;

    if (nch > 0)
        stage_chunk(x, start, min(CHUNK, end - start), buf_u32[0], tid);
    cp_commit();

    for (int ci = 0; ci < nch; ci++) {
        const int base = start + ci * CHUNK;
        const int n    = min(CHUNK, end - base);

        // prefetch next chunk into the other buffer
        if (ci + 1 < nch) {
            const int b2 = base + CHUNK;
            stage_chunk(x, b2, min(CHUNK, end - b2), buf_u32[(ci + 1) & 1], tid);
        }
        cp_commit();
        cp_wait1();            // chunk ci resident
        __syncthreads();       // (also covers wsh on first iter)

        const float* tile = bufs[ci & 1];

        // ---- scores: one warp per row (2 rows/warp at CHUNK=16) ----
        for (int c = warp; c < n; c += NTHREADS / 32) {
            const float* row = tile + c * D;
            float p = 0.0f;
            #pragma unroll
            for (int k = 0; k < D / 32; k++)
                p = fmaf(row[lane + 32 * k], wsh[lane + 32 * k], p);
            #pragma unroll
            for (int o = 16; o; o >>= 1) p += __shfl_xor_sync(0xffffffffu, p, o);
            if (lane == 0) scores[c] = p + bconst;
        }
        __syncthreads();

        // ---- per-thread online softmax (broadcast LDS, fully redundant
        //      across threads -> no extra barrier, no warp-0 serialization) ----
        float cm = -INFINITY;
        for (int c = 0; c < n; c++) cm = fmaxf(cm, scores[c]);
        const float m_new = fmaxf(m_run, cm);
        const float corr  = __expf(m_run - m_new);   // 0 when m_run == -inf

        // ---- fused exp + accumulate: thread owns column tid ----
        float a  = acc * corr;
        float ls = 0.0f;
        const float* tcol = tile + tid;
        #pragma unroll 4
        for (int c = 0; c < n; c++) {
            const float e = __expf(scores[c] - m_new);
            ls += e;
            a = fmaf(e, tcol[c * D], a);
        }
        s_run = s_run * corr + ls;
        m_run = m_new;
        acc   = a;
        __syncthreads();   // all reads of this buffer done before restage
    }

    out[(size_t)seg * D + tid] = (s_run > 0.0f) ? (acc / s_run) : 0.0f;
}

extern "C" void kernel_launch(void* const* d_in, const int* in_sizes, int n_in,
                              void* d_out, int out_size)
{
    const float* x     = (const float*)d_in[0];
    const float* w     = (const float*)d_in[1];
    const float* bptr  = (const float*)d_in[2];
    const int*   batch = (const int*)d_in[3];

    const int N = in_sizes[3];
    const int B = out_size / D;

    bounds_kernel<<<(N + 1 + 255) / 256, 256>>>(batch, N, B);

    cudaFuncSetAttribute(niche_attn_kernel,
                         cudaFuncAttributeMaxDynamicSharedMemorySize, SMEM_BYTES);
    niche_attn_kernel<<<B, NTHREADS, SMEM_BYTES>>>(x, w, bptr, (float*)d_out);
}

// round 8
// speedup vs baseline: 1.1386x; 1.1386x over previous
#include <cuda_runtime.h>
#include <cuda_bf16.h>
#include <stdint.h>
#include <math.h>

#define D 256
#define CHUNK 20
#define NTHREADS 256
#define MAXB 4100

// dynamic smem: 2 tiles + scores + w + red
#define SMEM_FLOATS (2 * CHUNK * D + 32 + D + 8)
#define SMEM_BYTES  (SMEM_FLOATS * 4)

__device__ int g_seg_start[MAXB];

// ---- kernel 1: segment boundaries from sorted batch (parallel diff-scatter) ----
__global__ void bounds_kernel(const int* __restrict__ batch, int N, int B) {
    int i = blockIdx.x * blockDim.x + threadIdx.x;
    if (i > N) return;
    int cur  = (i < N) ? batch[i]     : B;
    int prev = (i > 0) ? batch[i - 1] : -1;
    for (int b = prev + 1; b <= cur && b <= B; b++) g_seg_start[b] = i;
}

// ---- cp.async helpers ----
__device__ __forceinline__ void cp_async16(uint32_t dst_smem, const void* src) {
    asm volatile("cp.async.cg.shared.global [%0], [%1], 16;\n" :: "r"(dst_smem), "l"(src));
}
__device__ __forceinline__ void cp_commit() {
    asm volatile("cp.async.commit_group;\n");
}
__device__ __forceinline__ void cp_wait1() {
    asm volatile("cp.async.wait_group 1;\n");
}

__device__ __forceinline__ void stage_chunk(const float* __restrict__ x, int row0,
                                            int nrows, uint32_t buf_smem, int tid) {
    const char* src = reinterpret_cast<const char*>(x + (size_t)row0 * D);
    const int total = nrows * (D / 4);      // float4 count, <= 1280
    #pragma unroll
    for (int i = tid; i < total; i += NTHREADS)
        cp_async16(buf_smem + i * 16, src + (size_t)i * 16);
}

__global__ void __launch_bounds__(NTHREADS, 5)
niche_attn_kernel(const float* __restrict__ x,
                  const float* __restrict__ w,
                  const float* __restrict__ bptr,
                  float* __restrict__ out)
{
    extern __shared__ float smem[];
    float* tile0  = smem;                       // [CHUNK][D]
    float* tile1  = tile0 + CHUNK * D;          // [CHUNK][D]
    float* scores = tile1 + CHUNK * D;          // [32]
    float* wsh    = scores + 32;                // [D]
    float* red    = wsh + D;                    // [8]

    const int seg  = blockIdx.x;
    const int tid  = threadIdx.x;
    const int lane = tid & 31;
    const int warp = tid >> 5;

    const int start = g_seg_start[seg];
    const int end   = g_seg_start[seg + 1];

    wsh[tid] = w[tid];
    const float bconst = bptr[0];

    const uint32_t buf_u32[2] = {
        (uint32_t)__cvta_generic_to_shared(tile0),
        (uint32_t)__cvta_generic_to_shared(tile1)
    };
    float* const bufs[2] = { tile0, tile1 };

    const int nch = (end - start + CHUNK - 1) / CHUNK;

    float m_run = -INFINITY;
    float s_run = 0.0f;
    float acc   = 0.0f;

    if (nch > 0)
        stage_chunk(x, start, min(CHUNK, end - start), buf_u32[0], tid);
    cp_commit();

    for (int ci = 0; ci < nch; ci++) {
        const int base = start + ci * CHUNK;
        const int n    = min(CHUNK, end - base);

        // prefetch next chunk into the other buffer
        if (ci + 1 < nch) {
            const int b2 = base + CHUNK;
            stage_chunk(x, b2, min(CHUNK, end - b2), buf_u32[(ci + 1) & 1], tid);
        }
        cp_commit();
        cp_wait1();            // chunk ci resident
        __syncthreads();       // (also covers wsh on first iter)

        const float* tile = bufs[ci & 1];

        // ---- scores: one warp per row ----
        for (int c = warp; c < n; c += NTHREADS / 32) {
            const float* row = tile + c * D;
            float p = 0.0f;
            #pragma unroll
            for (int k = 0; k < D / 32; k++)
                p = fmaf(row[lane + 32 * k], wsh[lane + 32 * k], p);
            #pragma unroll
            for (int o = 16; o; o >>= 1) p += __shfl_xor_sync(0xffffffffu, p, o);
            if (lane == 0) scores[c] = p + bconst;
        }
        __syncthreads();

        // ---- warp 0: chunk softmax (n <= 20 fits one warp) ----
        if (warp == 0) {
            float sc = (lane < n) ? scores[lane] : -INFINITY;
            float cm = sc;
            #pragma unroll
            for (int o = 16; o; o >>= 1) cm = fmaxf(cm, __shfl_xor_sync(0xffffffffu, cm, o));
            const float m_new = fmaxf(m_run, cm);
            float e = (lane < n) ? __expf(sc - m_new) : 0.0f;
            if (lane < n) scores[lane] = e;
            float cs = e;
            #pragma unroll
            for (int o = 16; o; o >>= 1) cs += __shfl_xor_sync(0xffffffffu, cs, o);
            if (lane == 0) { red[0] = cm; red[1] = cs; }
        }
        __syncthreads();

        const float m_new = fmaxf(m_run, red[0]);
        const float corr  = __expf(m_run - m_new);   // 0 when m_run == -inf
        s_run = s_run * corr + red[1];
        m_run = m_new;

        // ---- accumulate: thread owns column tid ----
        float a = acc * corr;
        const float* tcol = tile + tid;
        int c = 0;
        for (; c + 3 < n; c += 4) {
            float e0 = scores[c + 0], e1 = scores[c + 1];
            float e2 = scores[c + 2], e3 = scores[c + 3];
            a = fmaf(e0, tcol[(c + 0) * D], a);
            a = fmaf(e1, tcol[(c + 1) * D], a);
            a = fmaf(e2, tcol[(c + 2) * D], a);
            a = fmaf(e3, tcol[(c + 3) * D], a);
        }
        for (; c < n; c++) a = fmaf(scores[c], tcol[c * D], a);
        acc = a;
        __syncthreads();   // all reads of this buffer done before restage
    }

    out[(size_t)seg * D + tid] = (s_run > 0.0f) ? (acc / s_run) : 0.0f;
}

extern "C" void kernel_launch(void* const* d_in, const int* in_sizes, int n_in,
                              void* d_out, int out_size)
{
    const float* x     = (const float*)d_in[0];
    const float* w     = (const float*)d_in[1];
    const float* bptr  = (const float*)d_in[2];
    const int*   batch = (const int*)d_in[3];

    const int N = in_sizes[3];
    const int B = out_size / D;

    bounds_kernel<<<(N + 1 + 255) / 256, 256>>>(batch, N, B);

    cudaFuncSetAttribute(niche_attn_kernel,
                         cudaFuncAttributeMaxDynamicSharedMemorySize, SMEM_BYTES);
    niche_attn_kernel<<<B, NTHREADS, SMEM_BYTES>>>(x, w, bptr, (float*)d_out);
}

// round 9
// speedup vs baseline: 1.3744x; 1.2072x over previous
#include <cuda_runtime.h>
#include <cuda_bf16.h>
#include <stdint.h>
#include <math.h>

#define D 256
#define NTHREADS 256
#define NWARPS (NTHREADS / 32)
#define MAXB 4100

__device__ int g_seg_start[MAXB];

// ---- kernel 1: segment boundaries from sorted batch (parallel diff-scatter) ----
__global__ void bounds_kernel(const int* __restrict__ batch, int N, int B) {
    int i = blockIdx.x * blockDim.x + threadIdx.x;
    if (i > N) return;
    int cur  = (i < N) ? batch[i]     : B;
    int prev = (i > 0) ? batch[i - 1] : -1;
    for (int b = prev + 1; b <= cur && b <= B; b++) g_seg_start[b] = i;
}

__global__ void __launch_bounds__(NTHREADS, 4)
niche_attn_kernel(const float* __restrict__ x,
                  const float* __restrict__ w,
                  const float* __restrict__ bptr,
                  float* __restrict__ out)
{
    __shared__ float comb[NWARPS * D];   // per-warp partial outputs
    __shared__ float wm[NWARPS], ws[NWARPS];

    const int seg  = blockIdx.x;
    const int tid  = threadIdx.x;
    const int lane = tid & 31;
    const int warp = tid >> 5;

    const int start = g_seg_start[seg];
    const int end   = g_seg_start[seg + 1];

    // per-lane slice of w: cols [4l..4l+3] and [128+4l..128+4l+3]
    const float4* w4 = reinterpret_cast<const float4*>(w);
    const float4 w0 = w4[lane];
    const float4 w1 = w4[32 + lane];
    const float bconst = bptr[0];

    const float4* xr = reinterpret_cast<const float4*>(x);

    // warp-local online softmax state (acc in registers)
    float m_w = -INFINITY;
    float s_w = 0.0f;
    float4 acc0 = make_float4(0.f, 0.f, 0.f, 0.f);
    float4 acc1 = make_float4(0.f, 0.f, 0.f, 0.f);

    int r = start + warp;
    float4 a0, a1;
    if (r < end) {
        const size_t base = (size_t)r * (D / 4);
        a0 = __ldg(xr + base + lane);
        a1 = __ldg(xr + base + 32 + lane);
    }

    for (; r < end; r += NWARPS) {
        // prefetch next row for this warp (issues before the reduce chain)
        const int rn = r + NWARPS;
        float4 b0, b1;
        if (rn < end) {
            const size_t nb = (size_t)rn * (D / 4);
            b0 = __ldg(xr + nb + lane);
            b1 = __ldg(xr + nb + 32 + lane);
        }

        // dot(row, w) : 8 FMA + butterfly
        float p;
        p = a0.x * w0.x;
        p = fmaf(a0.y, w0.y, p);
        p = fmaf(a0.z, w0.z, p);
        p = fmaf(a0.w, w0.w, p);
        p = fmaf(a1.x, w1.x, p);
        p = fmaf(a1.y, w1.y, p);
        p = fmaf(a1.z, w1.z, p);
        p = fmaf(a1.w, w1.w, p);
        #pragma unroll
        for (int o = 16; o; o >>= 1) p += __shfl_xor_sync(0xffffffffu, p, o);
        const float score = p + bconst;   // warp-uniform

        if (score <= m_w) {
            // common case: no new max
            const float e = __expf(score - m_w);
            s_w += e;
            acc0.x = fmaf(e, a0.x, acc0.x);
            acc0.y = fmaf(e, a0.y, acc0.y);
            acc0.z = fmaf(e, a0.z, acc0.z);
            acc0.w = fmaf(e, a0.w, acc0.w);
            acc1.x = fmaf(e, a1.x, acc1.x);
            acc1.y = fmaf(e, a1.y, acc1.y);
            acc1.z = fmaf(e, a1.z, acc1.z);
            acc1.w = fmaf(e, a1.w, acc1.w);
        } else {
            // new max: rescale (c = 0 when m_w was -inf)
            const float c = __expf(m_w - score);
            s_w = fmaf(s_w, c, 1.0f);
            acc0.x = fmaf(acc0.x, c, a0.x);
            acc0.y = fmaf(acc0.y, c, a0.y);
            acc0.z = fmaf(acc0.z, c, a0.z);
            acc0.w = fmaf(acc0.w, c, a0.w);
            acc1.x = fmaf(acc1.x, c, a1.x);
            acc1.y = fmaf(acc1.y, c, a1.y);
            acc1.z = fmaf(acc1.z, c, a1.z);
            acc1.w = fmaf(acc1.w, c, a1.w);
            m_w = score;
        }

        a0 = b0; a1 = b1;
    }

    // ---- stage warp partials ----
    float4* crow = reinterpret_cast<float4*>(comb + warp * D);
    crow[lane]      = acc0;
    crow[32 + lane] = acc1;
    if (lane == 0) { wm[warp] = m_w; ws[warp] = s_w; }
    __syncthreads();

    // ---- combine: thread tid owns output column tid ----
    float M = -INFINITY;
    #pragma unroll
    for (int i = 0; i < NWARPS; i++) M = fmaxf(M, wm[i]);

    float val = 0.0f, s_tot = 0.0f;
    #pragma unroll
    for (int i = 0; i < NWARPS; i++) {
        const float mi = wm[i];
        const float sc = (mi == -INFINITY) ? 0.0f : __expf(mi - M);
        s_tot = fmaf(ws[i], sc, s_tot);
        val   = fmaf(comb[i * D + tid], sc, val);
    }

    out[(size_t)seg * D + tid] = (s_tot > 0.0f) ? (val / s_tot) : 0.0f;
}

extern "C" void kernel_launch(void* const* d_in, const int* in_sizes, int n_in,
                              void* d_out, int out_size)
{
    const float* x     = (const float*)d_in[0];
    const float* w     = (const float*)d_in[1];
    const float* bptr  = (const float*)d_in[2];
    const int*   batch = (const int*)d_in[3];

    const int N = in_sizes[3];
    const int B = out_size / D;

    bounds_kernel<<<(N + 1 + 255) / 256, 256>>>(batch, N, B);
    niche_attn_kernel<<<B, NTHREADS>>>(x, w, bptr, (float*)d_out);
}

// round 10
// speedup vs baseline: 1.4696x; 1.0692x over previous
#include <cuda_runtime.h>
#include <cuda_bf16.h>
#include <stdint.h>
#include <math.h>

#define D 256
#define NTHREADS 256
#define NWARPS (NTHREADS / 32)
#define MAXB 4100

__device__ int g_seg_start[MAXB];

// ---- kernel 1: segment boundaries from sorted batch (parallel diff-scatter) ----
__global__ void bounds_kernel(const int* __restrict__ batch, int N, int B) {
    int i = blockIdx.x * blockDim.x + threadIdx.x;
    if (i > N) return;
    int cur  = (i < N) ? batch[i]     : B;
    int prev = (i > 0) ? batch[i - 1] : -1;
    for (int b = prev + 1; b <= cur && b <= B; b++) g_seg_start[b] = i;
}

__device__ __forceinline__ float dot8(const float4& a0, const float4& a1,
                                      const float4& w0, const float4& w1) {
    float p;
    p = a0.x * w0.x;
    p = fmaf(a0.y, w0.y, p);
    p = fmaf(a0.z, w0.z, p);
    p = fmaf(a0.w, w0.w, p);
    p = fmaf(a1.x, w1.x, p);
    p = fmaf(a1.y, w1.y, p);
    p = fmaf(a1.z, w1.z, p);
    p = fmaf(a1.w, w1.w, p);
    return p;
}

__global__ void __launch_bounds__(NTHREADS, 4)
niche_attn_kernel(const float* __restrict__ x,
                  const float* __restrict__ w,
                  const float* __restrict__ bptr,
                  float* __restrict__ out)
{
    __shared__ float comb[NWARPS * D];   // per-warp partial outputs
    __shared__ float wm[NWARPS], ws[NWARPS];

    const int seg  = blockIdx.x;
    const int tid  = threadIdx.x;
    const int lane = tid & 31;
    const int warp = tid >> 5;

    const int start = g_seg_start[seg];
    const int end   = g_seg_start[seg + 1];

    const float4* w4 = reinterpret_cast<const float4*>(w);
    const float4 w0 = w4[lane];
    const float4 w1 = w4[32 + lane];
    const float bconst = bptr[0];

    const float4* xr = reinterpret_cast<const float4*>(x);

    float m_w = -INFINITY;
    float s_w = 0.0f;
    float4 acc0 = make_float4(0.f, 0.f, 0.f, 0.f);
    float4 acc1 = make_float4(0.f, 0.f, 0.f, 0.f);

    int r = start + warp;
    float4 a0, a1, a2, a3;
    if (r < end) {
        const size_t b0 = (size_t)r * (D / 4);
        a0 = __ldg(xr + b0 + lane);
        a1 = __ldg(xr + b0 + 32 + lane);
    }
    if (r + 8 < end) {
        const size_t b1 = (size_t)(r + 8) * (D / 4);
        a2 = __ldg(xr + b1 + lane);
        a3 = __ldg(xr + b1 + 32 + lane);
    }

    // ---- main loop: 2 rows per iteration, 4 loads in flight ----
    for (; r + 8 < end; r += 2 * NWARPS) {
        const int rn0 = r + 16, rn1 = r + 24;
        float4 p0, p1, p2, p3;
        if (rn0 < end) {
            const size_t nb = (size_t)rn0 * (D / 4);
            p0 = __ldg(xr + nb + lane);
            p1 = __ldg(xr + nb + 32 + lane);
        }
        if (rn1 < end) {
            const size_t nb = (size_t)rn1 * (D / 4);
            p2 = __ldg(xr + nb + lane);
            p3 = __ldg(xr + nb + 32 + lane);
        }

        // two interleaved dot+butterfly chains
        float d0 = dot8(a0, a1, w0, w1);
        float d1 = dot8(a2, a3, w0, w1);
        #pragma unroll
        for (int o = 16; o; o >>= 1) {
            d0 += __shfl_xor_sync(0xffffffffu, d0, o);
            d1 += __shfl_xor_sync(0xffffffffu, d1, o);
        }
        const float s0 = d0 + bconst;   // warp-uniform
        const float s1 = d1 + bconst;

        const float m_new = fmaxf(m_w, fmaxf(s0, s1));
        const float e0 = __expf(s0 - m_new);
        const float e1 = __expf(s1 - m_new);
        if (m_new == m_w) {
            s_w += e0 + e1;
            acc0.x = fmaf(e0, a0.x, fmaf(e1, a2.x, acc0.x));
            acc0.y = fmaf(e0, a0.y, fmaf(e1, a2.y, acc0.y));
            acc0.z = fmaf(e0, a0.z, fmaf(e1, a2.z, acc0.z));
            acc0.w = fmaf(e0, a0.w, fmaf(e1, a2.w, acc0.w));
            acc1.x = fmaf(e0, a1.x, fmaf(e1, a3.x, acc1.x));
            acc1.y = fmaf(e0, a1.y, fmaf(e1, a3.y, acc1.y));
            acc1.z = fmaf(e0, a1.z, fmaf(e1, a3.z, acc1.z));
            acc1.w = fmaf(e0, a1.w, fmaf(e1, a3.w, acc1.w));
        } else {
            const float c = __expf(m_w - m_new);   // 0 when m_w == -inf
            s_w = fmaf(s_w, c, e0 + e1);
            acc0.x = fmaf(acc0.x, c, fmaf(e0, a0.x, e1 * a2.x));
            acc0.y = fmaf(acc0.y, c, fmaf(e0, a0.y, e1 * a2.y));
            acc0.z = fmaf(acc0.z, c, fmaf(e0, a0.z, e1 * a2.z));
            acc0.w = fmaf(acc0.w, c, fmaf(e0, a0.w, e1 * a2.w));
            acc1.x = fmaf(acc1.x, c, fmaf(e0, a1.x, e1 * a3.x));
            acc1.y = fmaf(acc1.y, c, fmaf(e0, a1.y, e1 * a3.y));
            acc1.z = fmaf(acc1.z, c, fmaf(e0, a1.z, e1 * a3.z));
            acc1.w = fmaf(acc1.w, c, fmaf(e0, a1.w, e1 * a3.w));
            m_w = m_new;
        }

        a0 = p0; a1 = p1; a2 = p2; a3 = p3;
    }

    // ---- tail: at most one row, already resident in a0/a1 ----
    if (r < end) {
        float d0 = dot8(a0, a1, w0, w1);
        #pragma unroll
        for (int o = 16; o; o >>= 1) d0 += __shfl_xor_sync(0xffffffffu, d0, o);
        const float s0 = d0 + bconst;
        if (s0 <= m_w) {
            const float e = __expf(s0 - m_w);
            s_w += e;
            acc0.x = fmaf(e, a0.x, acc0.x);
            acc0.y = fmaf(e, a0.y, acc0.y);
            acc0.z = fmaf(e, a0.z, acc0.z);
            acc0.w = fmaf(e, a0.w, acc0.w);
            acc1.x = fmaf(e, a1.x, acc1.x);
            acc1.y = fmaf(e, a1.y, acc1.y);
            acc1.z = fmaf(e, a1.z, acc1.z);
            acc1.w = fmaf(e, a1.w, acc1.w);
        } else {
            const float c = __expf(m_w - s0);   // 0 when m_w == -inf
            s_w = fmaf(s_w, c, 1.0f);
            acc0.x = fmaf(acc0.x, c, a0.x);
            acc0.y = fmaf(acc0.y, c, a0.y);
            acc0.z = fmaf(acc0.z, c, a0.z);
            acc0.w = fmaf(acc0.w, c, a0.w);
            acc1.x = fmaf(acc1.x, c, a1.x);
            acc1.y = fmaf(acc1.y, c, a1.y);
            acc1.z = fmaf(acc1.z, c, a1.z);
            acc1.w = fmaf(acc1.w, c, a1.w);
            m_w = s0;
        }
    }

    // ---- stage warp partials ----
    float4* crow = reinterpret_cast<float4*>(comb + warp * D);
    crow[lane]      = acc0;
    crow[32 + lane] = acc1;
    if (lane == 0) { wm[warp] = m_w; ws[warp] = s_w; }
    __syncthreads();

    // ---- combine: thread tid owns output column tid ----
    float M = -INFINITY;
    #pragma unroll
    for (int i = 0; i < NWARPS; i++) M = fmaxf(M, wm[i]);

    float val = 0.0f, s_tot = 0.0f;
    #pragma unroll
    for (int i = 0; i < NWARPS; i++) {
        const float mi = wm[i];
        const float sc = (mi == -INFINITY) ? 0.0f : __expf(mi - M);
        s_tot = fmaf(ws[i], sc, s_tot);
        val   = fmaf(comb[i * D + tid], sc, val);
    }

    out[(size_t)seg * D + tid] = (s_tot > 0.0f) ? (val / s_tot) : 0.0f;
}

extern "C" void kernel_launch(void* const* d_in, const int* in_sizes, int n_in,
                              void* d_out, int out_size)
{
    const float* x     = (const float*)d_in[0];
    const float* w     = (const float*)d_in[1];
    const float* bptr  = (const float*)d_in[2];
    const int*   batch = (const int*)d_in[3];

    const int N = in_sizes[3];
    const int B = out_size / D;

    bounds_kernel<<<(N + 1 + 255) / 256, 256>>>(batch, N, B);
    niche_attn_kernel<<<B, NTHREADS>>>(x, w, bptr, (float*)d_out);
}